// round 5
// baseline (speedup 1.0000x reference)
#include <cuda_runtime.h>
#include <cuda_bf16.h>

#define THREADS 256
#define GMAX 4096

__device__ float    g_acc[GMAX * 4];   // {count, sum11, sum24, pad}; zero-init at load
__device__ unsigned g_sem;             // zero-init at load

__global__ void __launch_bounds__(THREADS)
fused_kernel(const float* __restrict__ nf,
             const int*   __restrict__ batch,
             const float* __restrict__ W1,   // [32,2]
             const float* __restrict__ b1,   // [32]
             const float* __restrict__ W2,   // [1,32]
             const float* __restrict__ b2,   // [1]
             float* __restrict__ out,
             int N, int G, int nblocks) {
    const int lane = threadIdx.x & 31;
    const int i = blockIdx.x * THREADS + threadIdx.x;

    // ---- Phase 1: one node per thread (low MLP_p1 -> low cross-CTA spread) ----
    int   g = -1;
    float v0 = 0.0f, v1 = 0.0f;
    if (i < N) {
        g = __ldg(batch + i);
        const float* row = nf + (size_t)i * 128;
        v0 = __ldg(row + 11);   // MODIFIER_COL
        v1 = __ldg(row + 24);   // OWNER_COL
    }

    // ---- Phase 2: warp-segmented reduce (batch sorted -> contiguous runs) ----
    unsigned peers  = __match_any_sync(0xffffffffu, g);
    int      leader = __ffs(peers) - 1;
    int      cnt    = __popc(peers);
    #pragma unroll
    for (int off = 16; off > 0; off >>= 1) {
        float t0 = __shfl_down_sync(0xffffffffu, v0, off);
        float t1 = __shfl_down_sync(0xffffffffu, v1, off);
        if (lane + off < leader + cnt) { v0 += t0; v1 += t1; }
    }
    if (lane == leader && g >= 0) {
        atomicAdd(&g_acc[g * 4 + 0], (float)cnt);
        atomicAdd(&g_acc[g * 4 + 1], v0);
        atomicAdd(&g_acc[g * 4 + 2], v1);
    }

    // ---- Phase 3: last block runs the MLP, writes out, resets scratch ----
    __threadfence();
    __syncthreads();
    __shared__ int s_last;
    if (threadIdx.x == 0) {
        unsigned t = atomicAdd(&g_sem, 1u);
        s_last = (t == (unsigned)(nblocks - 1));
    }
    __syncthreads();
    if (!s_last) return;
    __threadfence();   // acquire: see all blocks' g_acc writes

    for (int gg = threadIdx.x; gg < G; gg += THREADS) {
        float cn = __ldcg(&g_acc[gg * 4 + 0]);
        float s0 = __ldcg(&g_acc[gg * 4 + 1]);
        float s1 = __ldcg(&g_acc[gg * 4 + 2]);
        float denom = fmaxf(cn, 1.0f);
        float a0 = 1.0f - s0 / denom;
        float a1 = 1.0f - s1 / denom;

        float acc = __ldg(b2);
        #pragma unroll
        for (int j = 0; j < 32; j++) {
            float h = fmaf(a0, __ldg(W1 + j * 2 + 0),
                      fmaf(a1, __ldg(W1 + j * 2 + 1), __ldg(b1 + j)));
            h = fmaxf(h, 0.0f);
            acc = fmaf(h, __ldg(W2 + j), acc);
        }
        float score = 1.0f / (1.0f + __expf(-acc));
        out[gg] = (cn > 0.0f) ? score : 0.0f;
    }

    __syncthreads();
    // Reset scratch for the next graph replay (first call sees static zeros).
    for (int k = threadIdx.x; k < G * 4; k += THREADS) g_acc[k] = 0.0f;
    if (threadIdx.x == 0) g_sem = 0u;
}

extern "C" void kernel_launch(void* const* d_in, const int* in_sizes, int n_in,
                              void* d_out, int out_size) {
    // metadata order: node_features, batch, graph_embedding(unused), W1, b1, W2, b2
    const float* nf    = (const float*)d_in[0];
    const int*   batch = (const int*)d_in[1];
    const float* W1    = (const float*)d_in[3];
    const float* b1    = (const float*)d_in[4];
    const float* W2    = (const float*)d_in[5];
    const float* b2    = (const float*)d_in[6];
    float*       out   = (float*)d_out;

    int N = in_sizes[1];   // number of nodes
    int G = out_size;      // number of graphs
    if (G > GMAX) G = GMAX;

    int nblocks = (N + THREADS - 1) / THREADS;
    fused_kernel<<<nblocks, THREADS>>>(nf, batch, W1, b1, W2, b2, out, N, G, nblocks);
}

// round 6
// speedup vs baseline: 1.1097x; 1.1097x over previous
#include <cuda_runtime.h>
#include <cuda_bf16.h>

#define THREADS 256
#define GMAX 4096

__device__ float    g_acc[GMAX * 4];   // {count, sum11, sum24, pad}; zero-init at load
__device__ unsigned g_sem;             // zero-init at load

__global__ void __launch_bounds__(THREADS)
fused_kernel(const float* __restrict__ nf,
             const int*   __restrict__ batch,
             const float* __restrict__ W1,   // [32,2]
             const float* __restrict__ b1,   // [32]
             const float* __restrict__ W2,   // [1,32]
             const float* __restrict__ b2,   // [1]
             float* __restrict__ out,
             int N, int G, int nblocks) {
    const int lane = threadIdx.x & 31;
    const int i = blockIdx.x * THREADS + threadIdx.x;

    // ---- Phase 1: one node per thread ----
    int   g = -1;
    float v0 = 0.0f, v1 = 0.0f;
    if (i < N) {
        g = __ldg(batch + i);
        const float* row = nf + (size_t)i * 128;
        v0 = __ldg(row + 11);   // MODIFIER_COL
        v1 = __ldg(row + 24);   // OWNER_COL
    }

    // ---- Phase 2: warp-segmented reduce (batch sorted -> contiguous runs) ----
    unsigned peers  = __match_any_sync(0xffffffffu, g);
    int      leader = __ffs(peers) - 1;
    int      cnt    = __popc(peers);
    #pragma unroll
    for (int off = 16; off > 0; off >>= 1) {
        float t0 = __shfl_down_sync(0xffffffffu, v0, off);
        float t1 = __shfl_down_sync(0xffffffffu, v1, off);
        if (lane + off < leader + cnt) { v0 += t0; v1 += t1; }
    }
    if (lane == leader && g >= 0) {
        atomicAdd(&g_acc[g * 4 + 0], (float)cnt);
        atomicAdd(&g_acc[g * 4 + 1], v0);
        atomicAdd(&g_acc[g * 4 + 2], v1);
    }

    // ---- Phase 3: last-block-done via ONE acq_rel L2 atomic per block ----
    // __syncthreads() orders all block threads' atomics before thread 0's
    // release; the last arriver's acquire makes all blocks' g_acc visible.
    // NO per-thread __threadfence() (GPU-scope membar = CCTL.IVALL, huge cost).
    __syncthreads();
    __shared__ int s_last;
    if (threadIdx.x == 0) {
        unsigned old;
        asm volatile("atom.acq_rel.gpu.global.add.u32 %0, [%1], %2;"
                     : "=r"(old) : "l"(&g_sem), "r"(1u) : "memory");
        s_last = (old == (unsigned)(nblocks - 1));
    }
    __syncthreads();
    if (!s_last) return;

    for (int gg = threadIdx.x; gg < G; gg += THREADS) {
        float cn = __ldcg(&g_acc[gg * 4 + 0]);
        float s0 = __ldcg(&g_acc[gg * 4 + 1]);
        float s1 = __ldcg(&g_acc[gg * 4 + 2]);
        float denom = fmaxf(cn, 1.0f);
        float a0 = 1.0f - s0 / denom;
        float a1 = 1.0f - s1 / denom;

        float acc = __ldg(b2);
        #pragma unroll
        for (int j = 0; j < 32; j++) {
            float h = fmaf(a0, __ldg(W1 + j * 2 + 0),
                      fmaf(a1, __ldg(W1 + j * 2 + 1), __ldg(b1 + j)));
            h = fmaxf(h, 0.0f);
            acc = fmaf(h, __ldg(W2 + j), acc);
        }
        float score = 1.0f / (1.0f + __expf(-acc));
        out[gg] = (cn > 0.0f) ? score : 0.0f;
    }

    __syncthreads();
    // Reset scratch for the next graph replay (first call sees static zeros;
    // kernel launch boundary makes these visible to the next replay).
    for (int k = threadIdx.x; k < G * 4; k += THREADS) g_acc[k] = 0.0f;
    if (threadIdx.x == 0) g_sem = 0u;
}

extern "C" void kernel_launch(void* const* d_in, const int* in_sizes, int n_in,
                              void* d_out, int out_size) {
    // metadata order: node_features, batch, graph_embedding(unused), W1, b1, W2, b2
    const float* nf    = (const float*)d_in[0];
    const int*   batch = (const int*)d_in[1];
    const float* W1    = (const float*)d_in[3];
    const float* b1    = (const float*)d_in[4];
    const float* W2    = (const float*)d_in[5];
    const float* b2    = (const float*)d_in[6];
    float*       out   = (float*)d_out;

    int N = in_sizes[1];   // number of nodes
    int G = out_size;      // number of graphs
    if (G > GMAX) G = GMAX;

    int nblocks = (N + THREADS - 1) / THREADS;
    fused_kernel<<<nblocks, THREADS>>>(nf, batch, W1, b1, W2, b2, out, N, G, nblocks);
}

// round 7
// speedup vs baseline: 1.5129x; 1.3633x over previous
#include <cuda_runtime.h>
#include <cuda_bf16.h>

#define THREADS 256
#define GMAX 4096

// {count, sum_col11, sum_col24, pad} per graph; zero-initialized at module load.
// mlp_reset_kernel re-zeroes after consuming, so every replay starts from zeros.
__device__ float g_acc[GMAX * 4];

// Segmented sum over sorted batch ids. One thread per node.
// Warp-level segmented reduction: only contiguous-run leaders do global atomics.
__global__ void __launch_bounds__(THREADS)
seg_reduce_kernel(const float* __restrict__ nf,
                  const int* __restrict__ batch,
                  int N) {
    int i = blockIdx.x * THREADS + threadIdx.x;
    int lane = threadIdx.x & 31;

    int g = -1;
    float v0 = 0.0f, v1 = 0.0f, c = 0.0f;
    if (i < N) {
        g = __ldg(batch + i);
        const float* row = nf + (size_t)i * 128;
        v0 = __ldg(row + 11);   // MODIFIER_COL
        v1 = __ldg(row + 24);   // OWNER_COL
        c  = 1.0f;
    }

    unsigned peers  = __match_any_sync(0xffffffffu, g);
    int      leader = __ffs(peers) - 1;
    int      cnt    = __popc(peers);

    #pragma unroll
    for (int off = 16; off > 0; off >>= 1) {
        float t0 = __shfl_down_sync(0xffffffffu, v0, off);
        float t1 = __shfl_down_sync(0xffffffffu, v1, off);
        float tc = __shfl_down_sync(0xffffffffu, c,  off);
        if (lane + off < leader + cnt) { v0 += t0; v1 += t1; c += tc; }
    }

    if (lane == leader && g >= 0) {
        atomicAdd(&g_acc[g * 4 + 0], c);
        atomicAdd(&g_acc[g * 4 + 1], v0);
        atomicAdd(&g_acc[g * 4 + 2], v1);
    }
}

// Consume accumulators, run tiny MLP, write out, and RESET accumulators to
// zero for the next graph replay (replaces the separate zero pass).
__global__ void mlp_reset_kernel(const float* __restrict__ W1,   // [32,2]
                                 const float* __restrict__ b1,   // [32]
                                 const float* __restrict__ W2,   // [1,32]
                                 const float* __restrict__ b2,   // [1]
                                 float* __restrict__ out, int G) {
    int g = blockIdx.x * blockDim.x + threadIdx.x;
    if (g >= G) return;

    float cn = g_acc[g * 4 + 0];
    float s0 = g_acc[g * 4 + 1];
    float s1 = g_acc[g * 4 + 2];

    // Reset for next replay (one thread owns these entries; launch boundary
    // orders this before the next replay's seg_reduce atomics).
    g_acc[g * 4 + 0] = 0.0f;
    g_acc[g * 4 + 1] = 0.0f;
    g_acc[g * 4 + 2] = 0.0f;

    float denom = fmaxf(cn, 1.0f);
    float a0 = 1.0f - s0 / denom;
    float a1 = 1.0f - s1 / denom;

    float acc = __ldg(b2);
    #pragma unroll
    for (int j = 0; j < 32; j++) {
        float h = fmaf(a0, __ldg(W1 + j * 2 + 0),
                  fmaf(a1, __ldg(W1 + j * 2 + 1), __ldg(b1 + j)));
        h = fmaxf(h, 0.0f);
        acc = fmaf(h, __ldg(W2 + j), acc);
    }
    float score = 1.0f / (1.0f + __expf(-acc));
    out[g] = (cn > 0.0f) ? score : 0.0f;
}

extern "C" void kernel_launch(void* const* d_in, const int* in_sizes, int n_in,
                              void* d_out, int out_size) {
    // metadata order: node_features, batch, graph_embedding(unused), W1, b1, W2, b2
    const float* nf    = (const float*)d_in[0];
    const int*   batch = (const int*)d_in[1];
    const float* W1    = (const float*)d_in[3];
    const float* b1    = (const float*)d_in[4];
    const float* W2    = (const float*)d_in[5];
    const float* b2    = (const float*)d_in[6];
    float*       out   = (float*)d_out;

    int N = in_sizes[1];   // number of nodes
    int G = out_size;      // number of graphs
    if (G > GMAX) G = GMAX;

    seg_reduce_kernel<<<(N + THREADS - 1) / THREADS, THREADS>>>(nf, batch, N);
    mlp_reset_kernel<<<(G + THREADS - 1) / THREADS, THREADS>>>(W1, b1, W2, b2, out, G);
}

// round 9
// speedup vs baseline: 1.5271x; 1.0094x over previous
#include <cuda_runtime.h>
#include <cuda_bf16.h>

#define THREADS 256
#define GMAX 4096

// {count, sum_col11, sum_col24, pad} per graph; zero-initialized at module load.
// mlp_reset_kernel re-zeroes after consuming, so every replay starts from zeros.
__device__ float4 g_acc[GMAX];

// Segmented sum over sorted batch ids. One thread per node.
// Warp-level segmented reduction: only contiguous-run leaders do global atomics.
__global__ void __launch_bounds__(THREADS)
seg_reduce_kernel(const float* __restrict__ nf,
                  const int* __restrict__ batch,
                  int N) {
    int i = blockIdx.x * THREADS + threadIdx.x;
    int lane = threadIdx.x & 31;

    int g = -1;
    float v0 = 0.0f, v1 = 0.0f, c = 0.0f;
    if (i < N) {
        g = __ldg(batch + i);
        const float* row = nf + (size_t)i * 128;
        v0 = __ldg(row + 11);   // MODIFIER_COL
        v1 = __ldg(row + 24);   // OWNER_COL
        c  = 1.0f;
    }

    unsigned peers  = __match_any_sync(0xffffffffu, g);
    int      leader = __ffs(peers) - 1;
    int      cnt    = __popc(peers);

    #pragma unroll
    for (int off = 16; off > 0; off >>= 1) {
        float t0 = __shfl_down_sync(0xffffffffu, v0, off);
        float t1 = __shfl_down_sync(0xffffffffu, v1, off);
        float tc = __shfl_down_sync(0xffffffffu, c,  off);
        if (lane + off < leader + cnt) { v0 += t0; v1 += t1; c += tc; }
    }

    if (lane == leader && g >= 0) {
        float* base = (float*)&g_acc[g];
        atomicAdd(base + 0, c);
        atomicAdd(base + 1, v0);
        atomicAdd(base + 2, v1);
    }
}

// Consume accumulators, run tiny MLP, write out, and RESET accumulators to
// zero for the next graph replay. Launched with PDL: starts while seg_reduce
// drains; cudaGridDependencySynchronize() blocks until seg's atomics are visible.
__global__ void mlp_reset_kernel(const float* __restrict__ W1,   // [32,2]
                                 const float* __restrict__ b1,   // [32]
                                 const float* __restrict__ W2,   // [1,32]
                                 const float* __restrict__ b2,   // [1]
                                 float* __restrict__ out, int G) {
    int g = blockIdx.x * blockDim.x + threadIdx.x;

#if __CUDA_ARCH__ >= 900
    cudaGridDependencySynchronize();
#endif

    if (g >= G) return;

    float4 a = g_acc[g];                       // one LDG.128
    g_acc[g] = make_float4(0.f, 0.f, 0.f, 0.f); // one STG.128 reset

    float denom = fmaxf(a.x, 1.0f);
    float a0 = 1.0f - a.y / denom;
    float a1 = 1.0f - a.z / denom;

    float acc = __ldg(b2);
    #pragma unroll
    for (int j = 0; j < 32; j++) {
        float h = fmaf(a0, __ldg(W1 + j * 2 + 0),
                  fmaf(a1, __ldg(W1 + j * 2 + 1), __ldg(b1 + j)));
        h = fmaxf(h, 0.0f);
        acc = fmaf(h, __ldg(W2 + j), acc);
    }
    float score = 1.0f / (1.0f + __expf(-acc));
    out[g] = (a.x > 0.0f) ? score : 0.0f;
}

extern "C" void kernel_launch(void* const* d_in, const int* in_sizes, int n_in,
                              void* d_out, int out_size) {
    // metadata order: node_features, batch, graph_embedding(unused), W1, b1, W2, b2
    const float* nf    = (const float*)d_in[0];
    const int*   batch = (const int*)d_in[1];
    const float* W1    = (const float*)d_in[3];
    const float* b1    = (const float*)d_in[4];
    const float* W2    = (const float*)d_in[5];
    const float* b2    = (const float*)d_in[6];
    float*       out   = (float*)d_out;

    int N = in_sizes[1];   // number of nodes
    int G = out_size;      // number of graphs
    if (G > GMAX) G = GMAX;

    seg_reduce_kernel<<<(N + THREADS - 1) / THREADS, THREADS>>>(nf, batch, N);

    // PDL launch of the epilogue: overlaps its launch latency with seg_reduce.
    cudaLaunchConfig_t cfg = {};
    cfg.gridDim  = dim3((G + THREADS - 1) / THREADS);
    cfg.blockDim = dim3(THREADS);
    cudaLaunchAttribute attr[1];
    attr[0].id = cudaLaunchAttributeProgrammaticStreamSerialization;
    attr[0].val.programmaticStreamSerializationAllowed = 1;
    cfg.attrs = attr;
    cfg.numAttrs = 1;
    cudaLaunchKernelEx(&cfg, mlp_reset_kernel, W1, b1, W2, b2, out, G);
}

// round 10
// speedup vs baseline: 1.6351x; 1.0707x over previous
#include <cuda_runtime.h>
#include <cuda_bf16.h>

#define THREADS 256
#define ITER 2
#define ROWS_PER_BLOCK (THREADS * ITER)
#define GMAX 4096

// {count, sum_col11, sum_col24, pad} per graph; zero-initialized at module load.
// mlp_reset_kernel re-zeroes after consuming, so every replay starts from zeros.
__device__ float4 g_acc[GMAX];

// Segmented sum over sorted batch ids. ITER nodes per thread, front-batched
// loads for ILP. Warp-segmented reduction: only contiguous-run leaders atomic.
__global__ void __launch_bounds__(THREADS)
seg_reduce_kernel(const float* __restrict__ nf,
                  const int* __restrict__ batch,
                  int N) {
    const int lane = threadIdx.x & 31;
    const int base = blockIdx.x * ROWS_PER_BLOCK;

    int   g[ITER];
    float v0[ITER], v1[ITER];
    #pragma unroll
    for (int it = 0; it < ITER; it++) {
        int i = base + it * THREADS + threadIdx.x;
        if (i < N) {
            g[it] = __ldg(batch + i);
            const float* row = nf + (size_t)i * 128;
            v0[it] = __ldcs(row + 11);   // MODIFIER_COL (streaming, no reuse)
            v1[it] = __ldcs(row + 24);   // OWNER_COL
        } else {
            g[it] = -1; v0[it] = 0.0f; v1[it] = 0.0f;
        }
    }

    #pragma unroll
    for (int it = 0; it < ITER; it++) {
        unsigned peers  = __match_any_sync(0xffffffffu, g[it]);
        int      leader = __ffs(peers) - 1;
        int      cnt    = __popc(peers);
        float a0 = v0[it], a1 = v1[it];
        #pragma unroll
        for (int off = 16; off > 0; off >>= 1) {
            float t0 = __shfl_down_sync(0xffffffffu, a0, off);
            float t1 = __shfl_down_sync(0xffffffffu, a1, off);
            if (lane + off < leader + cnt) { a0 += t0; a1 += t1; }
        }
        if (lane == leader && g[it] >= 0) {
            float* bp = (float*)&g_acc[g[it]];
            atomicAdd(bp + 0, (float)cnt);
            atomicAdd(bp + 1, a0);
            atomicAdd(bp + 2, a1);
        }
    }
}

// Consume accumulators, run tiny MLP, write out, RESET accumulators for the
// next replay. PDL: launches during seg_reduce; weights load before the
// dependency sync so only the g_acc read chain is exposed.
__global__ void mlp_reset_kernel(const float* __restrict__ W1,   // [32,2]
                                 const float* __restrict__ b1,   // [32]
                                 const float* __restrict__ W2,   // [1,32]
                                 const float* __restrict__ b2,   // [1]
                                 float* __restrict__ out, int G) {
    int g = blockIdx.x * blockDim.x + threadIdx.x;

    // Independent prologue: pull weights while the primary kernel drains.
    float w1a[32], w1b[32], w2[32];
    float bb1[32], bias2 = __ldg(b2);
    #pragma unroll
    for (int j = 0; j < 32; j++) {
        w1a[j] = __ldg(W1 + j * 2 + 0);
        w1b[j] = __ldg(W1 + j * 2 + 1);
        bb1[j] = __ldg(b1 + j);
        w2[j]  = __ldg(W2 + j);
    }

#if __CUDA_ARCH__ >= 900
    cudaGridDependencySynchronize();
#endif

    if (g >= G) return;

    float4 a = g_acc[g];                         // one LDG.128
    g_acc[g] = make_float4(0.f, 0.f, 0.f, 0.f);  // one STG.128 reset

    float denom = fmaxf(a.x, 1.0f);
    float a0 = 1.0f - a.y / denom;
    float a1 = 1.0f - a.z / denom;

    float acc = bias2;
    #pragma unroll
    for (int j = 0; j < 32; j++) {
        float h = fmaf(a0, w1a[j], fmaf(a1, w1b[j], bb1[j]));
        h = fmaxf(h, 0.0f);
        acc = fmaf(h, w2[j], acc);
    }
    float score = 1.0f / (1.0f + __expf(-acc));
    out[g] = (a.x > 0.0f) ? score : 0.0f;
}

extern "C" void kernel_launch(void* const* d_in, const int* in_sizes, int n_in,
                              void* d_out, int out_size) {
    // metadata order: node_features, batch, graph_embedding(unused), W1, b1, W2, b2
    const float* nf    = (const float*)d_in[0];
    const int*   batch = (const int*)d_in[1];
    const float* W1    = (const float*)d_in[3];
    const float* b1    = (const float*)d_in[4];
    const float* W2    = (const float*)d_in[5];
    const float* b2    = (const float*)d_in[6];
    float*       out   = (float*)d_out;

    int N = in_sizes[1];   // number of nodes
    int G = out_size;      // number of graphs
    if (G > GMAX) G = GMAX;

    int nblocks = (N + ROWS_PER_BLOCK - 1) / ROWS_PER_BLOCK;
    seg_reduce_kernel<<<nblocks, THREADS>>>(nf, batch, N);

    // PDL launch of the epilogue: overlaps its launch + weight loads with seg_reduce.
    cudaLaunchConfig_t cfg = {};
    cfg.gridDim  = dim3((G + THREADS - 1) / THREADS);
    cfg.blockDim = dim3(THREADS);
    cudaLaunchAttribute attr[1];
    attr[0].id = cudaLaunchAttributeProgrammaticStreamSerialization;
    attr[0].val.programmaticStreamSerializationAllowed = 1;
    cfg.attrs = attr;
    cfg.numAttrs = 1;
    cudaLaunchKernelEx(&cfg, mlp_reset_kernel, W1, b1, W2, b2, out, G);
}